// round 15
// baseline (speedup 1.0000x reference)
#include <cuda_runtime.h>
#include <cuda_fp16.h>
#include <math.h>

#define NN 100000
#define EE 1600000
#define EPSV 1e-16f
#define NEG_SLOPE 0.2f
#define FULL 0xffffffffu

// ---------------- scratch (device globals; allocation-free) ----------------
__device__ uint4   g_h1h[NN * 16];     // h1 [N,128] fp16       25.6 MB (16B-aligned)
__device__ float   g_as1[NN * 8];      // alpha_src1 [N,8]       3.2 MB
__device__ float   g_ad1[NN * 8];      // alpha_dst1 [N,8]       3.2 MB
__device__ uint4   g_out1h[NN * 16];   // elu(out1) [N,128] fp16 25.6 MB
__device__ __half2 g_g2h[NN * 20];     // g2 [N,40] fp16           8 MB
__device__ float   g_as2[NN];          // alpha_src2 [N]
__device__ float   g_ad2[NN];          // alpha_dst2 [N]
// CSR sort scratch (g_deg self-cleans: hist fills, scatter drains to 0)
__device__ int     g_deg[NN];
__device__ int     g_off[NN + 1];
__device__ int     g_ssrc[EE];         // src sorted by dst      6.4 MB
__device__ int     g_bsum[128];

// ---------------- helpers ----------------
__device__ __forceinline__ void fma4(float4& a, float s, float4 b) {
    a.x += s * b.x; a.y += s * b.y; a.z += s * b.z; a.w += s * b.w;
}
__device__ __forceinline__ float dot4(float4 a, float4 b) {
    return a.x * b.x + a.y * b.y + a.z * b.z + a.w * b.w;
}
__device__ __forceinline__ float leaky_exp(float e) {
    float t = e > 0.f ? e : NEG_SLOPE * e;
    return __expf(t);
}
__device__ __forceinline__ uint2 pack_half4(float4 v) {
    __half2 p0 = __floats2half2_rn(v.x, v.y);
    __half2 p1 = __floats2half2_rn(v.z, v.w);
    return make_uint2(*(unsigned*)&p0, *(unsigned*)&p1);
}
// ---- packed fp32x2 (Blackwell FFMA2) ----
__device__ __forceinline__ unsigned long long pk2(float lo, float hi) {
    unsigned long long r;
    asm("mov.b64 %0, {%1, %2};" : "=l"(r) : "f"(lo), "f"(hi));
    return r;
}
__device__ __forceinline__ unsigned long long fma2(
    unsigned long long a, unsigned long long b, unsigned long long c) {
    unsigned long long d;
    asm("fma.rn.f32x2 %0, %1, %2, %3;" : "=l"(d) : "l"(a), "l"(b), "l"(c));
    return d;
}
__device__ __forceinline__ float2 upk2(unsigned long long v) {
    float2 f;
    asm("mov.b64 {%0, %1}, %2;" : "=f"(f.x), "=f"(f.y) : "l"(v));
    return f;
}

// ---------------- S1. histogram of dst (4 edges/thread) ----------------
__global__ __launch_bounds__(256) void hist_kernel(const int* __restrict__ dst) {
    int i = blockIdx.x * 256 + threadIdx.x;
    if (i < EE / 4) {
        int4 d = __ldcs(&((const int4*)dst)[i]);
        atomicAdd(&g_deg[d.x], 1);
        atomicAdd(&g_deg[d.y], 1);
        atomicAdd(&g_deg[d.z], 1);
        atomicAdd(&g_deg[d.w], 1);
    }
}

// ---------------- S2a. block-level exclusive scan of degrees ----------------
__global__ __launch_bounds__(1024) void scan1_kernel() {
    int t = threadIdx.x;
    int i = blockIdx.x * 1024 + t;
    int v = (i < NN) ? g_deg[i] : 0;
    int lane = t & 31, w = t >> 5;
    int x = v;
    #pragma unroll
    for (int o = 1; o < 32; o <<= 1) {
        int y = __shfl_up_sync(FULL, x, o);
        if (lane >= o) x += y;
    }
    __shared__ int wt[32];
    if (lane == 31) wt[w] = x;
    __syncthreads();
    if (w == 0) {
        int z = wt[lane];
        #pragma unroll
        for (int o = 1; o < 32; o <<= 1) {
            int y = __shfl_up_sync(FULL, z, o);
            if (lane >= o) z += y;
        }
        wt[lane] = z;
    }
    __syncthreads();
    int pre = (w ? wt[w - 1] : 0);
    if (i < NN) g_off[i] = pre + x - v;      // block-local exclusive
    if (t == 1023) g_bsum[blockIdx.x] = wt[31];
}

// ---------------- S2b. add block prefix ----------------
__global__ __launch_bounds__(1024) void scanB_kernel() {
    __shared__ int s[128];
    __shared__ int blockpre;
    int t = threadIdx.x;
    if (t < 128) s[t] = (t < 98) ? g_bsum[t] : 0;
    __syncthreads();
    if (t == 0) {
        int run = 0;
        for (int b = 0; b < blockIdx.x; b++) run += s[b];
        blockpre = run;
    }
    __syncthreads();
    int i = blockIdx.x * 1024 + t;
    if (i < NN) g_off[i] += blockpre;
    if (i == 0) g_off[NN] = EE;
}

// ---------------- S3. scatter (4 edges/thread; drains g_deg to 0) -----------
__global__ __launch_bounds__(256) void scatter_kernel(
    const int* __restrict__ src, const int* __restrict__ dst)
{
    int i = blockIdx.x * 256 + threadIdx.x;
    if (i < EE / 4) {
        int4 d = __ldcs(&((const int4*)dst)[i]);
        int4 s = __ldcs(&((const int4*)src)[i]);
        int p0 = g_off[d.x] + atomicSub(&g_deg[d.x], 1) - 1;
        int p1 = g_off[d.y] + atomicSub(&g_deg[d.y], 1) - 1;
        int p2 = g_off[d.z] + atomicSub(&g_deg[d.z], 1) - 1;
        int p3 = g_off[d.w] + atomicSub(&g_deg[d.w], 1) - 1;
        __stcs(&g_ssrc[p0], s.x);
        __stcs(&g_ssrc[p1], s.y);
        __stcs(&g_ssrc[p2], s.z);
        __stcs(&g_ssrc[p3], s.w);
    }
}

// ---------------- 1. GEMM1 (register-tiled, f32x2): h1(fp16)=x@W1 -----------
__global__ __launch_bounds__(256) void gemm1_kernel(
    const float* __restrict__ x, const float* __restrict__ W1,
    const float* __restrict__ a_src, const float* __restrict__ a_dst)
{
    extern __shared__ float smem[];
    float4* sW4 = (float4*)smem;                 // [k*32 + c4] (64 k-rows)
    float4* sx4 = (float4*)(smem + 64 * 128);    // [n*32 + k4]
    const ulonglong2* sW2 = (const ulonglong2*)smem;
    const int tid = threadIdx.x;
    const int cx = tid & 31;      // col quad
    const int ny = tid >> 5;      // node group of 8
    const int nbase = blockIdx.x * 64;
    const float4* W4 = (const float4*)W1;
    const float4* x4 = (const float4*)x;

    #pragma unroll
    for (int it = 0; it < 8; it++) {             // x: 2048 f4
        int f = tid + it * 256;
        int gn = nbase + (f >> 5);
        sx4[f] = (gn < NN) ? x4[(size_t)gn * 32 + (f & 31)]
                           : make_float4(0.f, 0.f, 0.f, 0.f);
    }

    unsigned long long c2[8][2];
    #pragma unroll
    for (int i = 0; i < 8; i++) { c2[i][0] = 0ull; c2[i][1] = 0ull; }

    #pragma unroll
    for (int ch = 0; ch < 2; ch++) {
        if (ch) __syncthreads();                 // drain reads of prev sW
        #pragma unroll
        for (int it = 0; it < 8; it++) {         // W chunk: 2048 f4
            int f = tid + it * 256;
            sW4[f] = W4[(ch * 64 + (f >> 5)) * 32 + (f & 31)];
        }
        __syncthreads();
        #pragma unroll 4
        for (int k = 0; k < 64; k += 4) {
            ulonglong2 w0 = sW2[(k + 0) * 32 + cx];
            ulonglong2 w1 = sW2[(k + 1) * 32 + cx];
            ulonglong2 w2 = sW2[(k + 2) * 32 + cx];
            ulonglong2 w3 = sW2[(k + 3) * 32 + cx];
            #pragma unroll
            for (int i = 0; i < 8; i++) {
                float4 xv = sx4[(ny * 8 + i) * 32 + ((ch * 64 + k) >> 2)];
                unsigned long long d0 = pk2(xv.x, xv.x);
                unsigned long long d1 = pk2(xv.y, xv.y);
                unsigned long long d2 = pk2(xv.z, xv.z);
                unsigned long long d3 = pk2(xv.w, xv.w);
                c2[i][0] = fma2(d0, w0.x, c2[i][0]);
                c2[i][1] = fma2(d0, w0.y, c2[i][1]);
                c2[i][0] = fma2(d1, w1.x, c2[i][0]);
                c2[i][1] = fma2(d1, w1.y, c2[i][1]);
                c2[i][0] = fma2(d2, w2.x, c2[i][0]);
                c2[i][1] = fma2(d2, w2.y, c2[i][1]);
                c2[i][0] = fma2(d3, w3.x, c2[i][0]);
                c2[i][1] = fma2(d3, w3.y, c2[i][1]);
            }
        }
    }

    // epilogue: unpack, store h1 (fp16) + per-head alpha dots
    const int head = cx >> 2, cq = cx & 3;
    const float4 asv = ((const float4*)a_src)[head * 4 + cq];
    const float4 adv = ((const float4*)a_dst)[head * 4 + cq];
    #pragma unroll
    for (int i = 0; i < 8; i++) {
        int gn = nbase + ny * 8 + i;
        float2 lo = upk2(c2[i][0]);
        float2 hi = upk2(c2[i][1]);
        float4 ci = make_float4(lo.x, lo.y, hi.x, hi.y);
        float ps = dot4(ci, asv);
        float pd = dot4(ci, adv);
        ps += __shfl_xor_sync(FULL, ps, 1); ps += __shfl_xor_sync(FULL, ps, 2);
        pd += __shfl_xor_sync(FULL, pd, 1); pd += __shfl_xor_sync(FULL, pd, 2);
        if (gn < NN) {
            ((uint2*)g_h1h)[gn * 32 + cx] = pack_half4(ci);
            if (cq == 0) { g_as1[gn * 8 + head] = ps; g_ad1[gn * 8 + head] = pd; }
        }
    }
}

// ---------------- 2. L1 aggregate: warp/node, 8 edges in flight -------------
// lanes 0-15 = even edges, 16-31 = odd edges; each lane owns 8 channels.
// Inner loop: 4 steps per half = 8 edges/warp-iter, 4 uint4 gathers in flight.
__global__ __launch_bounds__(256) void agg1_kernel(const float* __restrict__ b1)
{
    const int n = (blockIdx.x * 256 + threadIdx.x) >> 5;   // node (grid exact)
    const int l = threadIdx.x & 31;
    const int half = l >> 4;       // which edge of the pair
    const int ll = l & 15;         // channel-group lane (8 channels)
    const int headl = ll >> 1;     // head of channels ll*8..ll*8+7
    const int beg = g_off[n], end = g_off[n + 1];
    const float adp = g_ad1[n * 8 + headl];

    float den = 0.f;
    float a0=0.f,a1=0.f,a2=0.f,a3=0.f,a4=0.f,a5=0.f,a6=0.f,a7=0.f;

    for (int base = beg; base < end; base += 32) {
        const int je = min(32, end - base);
        const int sj = (l < je) ? __ldg(&g_ssrc[base + l]) : 0;
        const int nst = (je + 1) >> 1;
        int i = 0;
        #pragma unroll 1
        for (; i + 4 <= nst; i += 4) {
            int e0i = 2 * i + half, e1i = e0i + 2, e2i = e0i + 4, e3i = e0i + 6;
            int s0 = __shfl_sync(FULL, sj, e0i);
            int s1 = __shfl_sync(FULL, sj, e1i);
            int s2 = __shfl_sync(FULL, sj, e2i);
            int s3 = __shfl_sync(FULL, sj, e3i);
            float x0 = leaky_exp(__ldg(&g_as1[s0 * 8 + headl]) + adp);
            float x1 = leaky_exp(__ldg(&g_as1[s1 * 8 + headl]) + adp);
            float x2 = leaky_exp(__ldg(&g_as1[s2 * 8 + headl]) + adp);
            float x3 = leaky_exp(__ldg(&g_as1[s3 * 8 + headl]) + adp);
            x0 = (e0i < je) ? x0 : 0.f;
            x1 = (e1i < je) ? x1 : 0.f;
            x2 = (e2i < je) ? x2 : 0.f;
            x3 = (e3i < je) ? x3 : 0.f;
            uint4 p0 = __ldg(&g_h1h[s0 * 16 + ll]);
            uint4 p1 = __ldg(&g_h1h[s1 * 16 + ll]);
            uint4 p2 = __ldg(&g_h1h[s2 * 16 + ll]);
            uint4 p3 = __ldg(&g_h1h[s3 * 16 + ll]);
            den += (x0 + x1) + (x2 + x3);
            float2 q;
            q = __half22float2(*(__half2*)&p0.x); a0 += x0*q.x; a1 += x0*q.y;
            q = __half22float2(*(__half2*)&p0.y); a2 += x0*q.x; a3 += x0*q.y;
            q = __half22float2(*(__half2*)&p0.z); a4 += x0*q.x; a5 += x0*q.y;
            q = __half22float2(*(__half2*)&p0.w); a6 += x0*q.x; a7 += x0*q.y;
            q = __half22float2(*(__half2*)&p1.x); a0 += x1*q.x; a1 += x1*q.y;
            q = __half22float2(*(__half2*)&p1.y); a2 += x1*q.x; a3 += x1*q.y;
            q = __half22float2(*(__half2*)&p1.z); a4 += x1*q.x; a5 += x1*q.y;
            q = __half22float2(*(__half2*)&p1.w); a6 += x1*q.x; a7 += x1*q.y;
            q = __half22float2(*(__half2*)&p2.x); a0 += x2*q.x; a1 += x2*q.y;
            q = __half22float2(*(__half2*)&p2.y); a2 += x2*q.x; a3 += x2*q.y;
            q = __half22float2(*(__half2*)&p2.z); a4 += x2*q.x; a5 += x2*q.y;
            q = __half22float2(*(__half2*)&p2.w); a6 += x2*q.x; a7 += x2*q.y;
            q = __half22float2(*(__half2*)&p3.x); a0 += x3*q.x; a1 += x3*q.y;
            q = __half22float2(*(__half2*)&p3.y); a2 += x3*q.x; a3 += x3*q.y;
            q = __half22float2(*(__half2*)&p3.z); a4 += x3*q.x; a5 += x3*q.y;
            q = __half22float2(*(__half2*)&p3.w); a6 += x3*q.x; a7 += x3*q.y;
        }
        #pragma unroll 1
        for (; i < nst; i++) {
            int ei = 2 * i + half;
            int s = __shfl_sync(FULL, sj, ei);
            float e = leaky_exp(__ldg(&g_as1[s * 8 + headl]) + adp);
            e = (ei < je) ? e : 0.f;
            uint4 p = __ldg(&g_h1h[s * 16 + ll]);
            den += e;
            float2 q;
            q = __half22float2(*(__half2*)&p.x); a0 += e*q.x; a1 += e*q.y;
            q = __half22float2(*(__half2*)&p.y); a2 += e*q.x; a3 += e*q.y;
            q = __half22float2(*(__half2*)&p.z); a4 += e*q.x; a5 += e*q.y;
            q = __half22float2(*(__half2*)&p.w); a6 += e*q.x; a7 += e*q.y;
        }
    }
    // combine halves (all lanes converged)
    a0 += __shfl_xor_sync(FULL, a0, 16); a1 += __shfl_xor_sync(FULL, a1, 16);
    a2 += __shfl_xor_sync(FULL, a2, 16); a3 += __shfl_xor_sync(FULL, a3, 16);
    a4 += __shfl_xor_sync(FULL, a4, 16); a5 += __shfl_xor_sync(FULL, a5, 16);
    a6 += __shfl_xor_sync(FULL, a6, 16); a7 += __shfl_xor_sync(FULL, a7, 16);
    den += __shfl_xor_sync(FULL, den, 16);

    const float rinv = 1.f / (den + EPSV);
    const float4* b14 = (const float4*)b1;
    float4 bA = b14[ll * 2], bB = b14[ll * 2 + 1];
    float v0 = bA.x + a0 * rinv, v1 = bA.y + a1 * rinv;
    float v2 = bA.z + a2 * rinv, v3 = bA.w + a3 * rinv;
    float v4 = bB.x + a4 * rinv, v5 = bB.y + a5 * rinv;
    float v6 = bB.z + a6 * rinv, v7 = bB.w + a7 * rinv;
    v0 = v0 > 0.f ? v0 : __expf(v0) - 1.f;
    v1 = v1 > 0.f ? v1 : __expf(v1) - 1.f;
    v2 = v2 > 0.f ? v2 : __expf(v2) - 1.f;
    v3 = v3 > 0.f ? v3 : __expf(v3) - 1.f;
    v4 = v4 > 0.f ? v4 : __expf(v4) - 1.f;
    v5 = v5 > 0.f ? v5 : __expf(v5) - 1.f;
    v6 = v6 > 0.f ? v6 : __expf(v6) - 1.f;
    v7 = v7 > 0.f ? v7 : __expf(v7) - 1.f;
    if (half == 0) {
        uint4 o;
        __half2 t0 = __floats2half2_rn(v0, v1); o.x = *(unsigned*)&t0;
        __half2 t1 = __floats2half2_rn(v2, v3); o.y = *(unsigned*)&t1;
        __half2 t2 = __floats2half2_rn(v4, v5); o.z = *(unsigned*)&t2;
        __half2 t3 = __floats2half2_rn(v6, v7); o.w = *(unsigned*)&t3;
        g_out1h[n * 16 + ll] = o;
    }
}

// ---------------- 3. GEMM2 (f32x2, double-buffered): g2(fp16) ---------------
__global__ __launch_bounds__(256) void gemm2_kernel(
    const float* __restrict__ W2, const float* __restrict__ a_src,
    const float* __restrict__ a_dst)
{
    __shared__ float4 sW[128 * 10];
    __shared__ float4 sas[10], sad[10];
    __shared__ float  sx[256 * 17];
    const int tid = threadIdx.x;
    const int node = blockIdx.x * 256 + tid;
    const float4* W4 = (const float4*)W2;
    const ulonglong2* sW2p = (const ulonglong2*)sW;
    #pragma unroll
    for (int it = 0; it < 5; it++) sW[tid + it * 256] = W4[tid + it * 256];
    if (tid < 10) { sas[tid] = ((const float4*)a_src)[tid];
                    sad[tid] = ((const float4*)a_dst)[tid]; }
    const unsigned* hinw = (const unsigned*)g_out1h;   // raw half2 words

    unsigned long long acc2[10][2];
    #pragma unroll
    for (int j = 0; j < 10; j++) { acc2[j][0] = 0ull; acc2[j][1] = 0ull; }

    // register double-buffer: 8 raw half2 words per thread per chunk
    unsigned buf[8];
    #pragma unroll
    for (int it = 0; it < 8; it++) {
        int f = tid + it * 256;
        int nl2 = f >> 3, kp = f & 7;
        int gn = blockIdx.x * 256 + nl2;
        buf[it] = (gn < NN) ? __ldg(&hinw[(size_t)gn * 64 + kp]) : 0u;
    }

    for (int kc = 0; kc < 8; kc++) {
        __syncthreads();
        #pragma unroll
        for (int it = 0; it < 8; it++) {             // store current chunk
            int f = tid + it * 256;
            int nl2 = f >> 3, kp = f & 7;
            float2 fv = __half22float2(*(__half2*)&buf[it]);
            sx[nl2 * 17 + kp * 2 + 0] = fv.x;
            sx[nl2 * 17 + kp * 2 + 1] = fv.y;
        }
        if (kc < 7) {                                // prefetch next chunk
            #pragma unroll
            for (int it = 0; it < 8; it++) {
                int f = tid + it * 256;
                int nl2 = f >> 3, kp = f & 7;
                int gn = blockIdx.x * 256 + nl2;
                buf[it] = (gn < NN)
                    ? __ldg(&hinw[(size_t)gn * 64 + (kc + 1) * 8 + kp]) : 0u;
            }
        }
        __syncthreads();
        #pragma unroll
        for (int k = 0; k < 16; k++) {
            float xv = sx[tid * 17 + k];
            unsigned long long xd = pk2(xv, xv);
            const ulonglong2* wr = &sW2p[(kc * 16 + k) * 10];
            #pragma unroll
            for (int j = 0; j < 10; j++) {
                ulonglong2 w = wr[j];
                acc2[j][0] = fma2(xd, w.x, acc2[j][0]);
                acc2[j][1] = fma2(xd, w.y, acc2[j][1]);
            }
        }
    }
    if (node < NN) {
        float s = 0.f, d = 0.f;
        float4 accf[10];
        #pragma unroll
        for (int j = 0; j < 10; j++) {
            float2 lo = upk2(acc2[j][0]);
            float2 hi = upk2(acc2[j][1]);
            accf[j] = make_float4(lo.x, lo.y, hi.x, hi.y);
            s += dot4(accf[j], sas[j]);
            d += dot4(accf[j], sad[j]);
        }
        #pragma unroll
        for (int j = 0; j < 10; j++)
            *(uint2*)&g_g2h[node * 20 + 2 * j] = pack_half4(accf[j]);
        g_as2[node] = s;
        g_ad2[node] = d;
    }
}

// ---------------- 4. L2 fused aggregate: TWO nodes per warp -----------------
__global__ __launch_bounds__(256) void agg2_kernel(
    const float* __restrict__ b2, float* __restrict__ out)
{
    const int w = (blockIdx.x * 256 + threadIdx.x) >> 5;   // warp id
    const int l = threadIdx.x & 31;
    const int half = l >> 4, ll = l & 15;
    const unsigned HM = 0xFFFFu << (half * 16);            // half-local mask
    const int n = 2 * w + half;                            // NN even: exact
    const int beg = g_off[n], end = g_off[n + 1];
    const float ad2n = g_ad2[n];
    const bool act = ll < 10;
    const uint2* g24 = (const uint2*)g_g2h;      // [n*10 + c] -> 4 halves

    float den = 0.f;
    float4 acc = make_float4(0.f, 0.f, 0.f, 0.f);

    int nIter = (end - beg + 15) >> 4;
    int oIter = __shfl_xor_sync(FULL, nIter, 16);
    const int mIter = max(nIter, oIter);

    for (int it = 0; it < mIter; it++) {
        const int base = beg + it * 16;
        const int je = min(16, end - base);      // may be <= 0 for this half
        const int sj = (ll < je && je > 0) ? __ldg(&g_ssrc[base + ll]) : 0;
        int k = 0;
        #pragma unroll 1
        for (; k + 4 <= je; k += 4) {
            int s0 = __shfl_sync(HM, sj, k,     16);
            int s1 = __shfl_sync(HM, sj, k + 1, 16);
            int s2 = __shfl_sync(HM, sj, k + 2, 16);
            int s3 = __shfl_sync(HM, sj, k + 3, 16);
            float e0 = leaky_exp(__ldg(&g_as2[s0]) + ad2n);
            float e1 = leaky_exp(__ldg(&g_as2[s1]) + ad2n);
            float e2 = leaky_exp(__ldg(&g_as2[s2]) + ad2n);
            float e3 = leaky_exp(__ldg(&g_as2[s3]) + ad2n);
            den += (e0 + e1) + (e2 + e3);
            if (act) {
                uint2 p0 = __ldg(&g24[s0 * 10 + ll]);
                uint2 p1 = __ldg(&g24[s1 * 10 + ll]);
                uint2 p2 = __ldg(&g24[s2 * 10 + ll]);
                uint2 p3 = __ldg(&g24[s3 * 10 + ll]);
                float2 a0 = __half22float2(*(__half2*)&p0.x), b0 = __half22float2(*(__half2*)&p0.y);
                float2 a1 = __half22float2(*(__half2*)&p1.x), b1v = __half22float2(*(__half2*)&p1.y);
                float2 a2 = __half22float2(*(__half2*)&p2.x), b2v = __half22float2(*(__half2*)&p2.y);
                float2 a3 = __half22float2(*(__half2*)&p3.x), b3 = __half22float2(*(__half2*)&p3.y);
                acc.x += e0 * a0.x + e1 * a1.x + e2 * a2.x + e3 * a3.x;
                acc.y += e0 * a0.y + e1 * a1.y + e2 * a2.y + e3 * a3.y;
                acc.z += e0 * b0.x + e1 * b1v.x + e2 * b2v.x + e3 * b3.x;
                acc.w += e0 * b0.y + e1 * b1v.y + e2 * b2v.y + e3 * b3.y;
            }
        }
        #pragma unroll 1
        for (; k < je; k++) {
            int s = __shfl_sync(HM, sj, k, 16);
            float e = leaky_exp(__ldg(&g_as2[s]) + ad2n);
            den += e;
            if (act) {
                uint2 p = __ldg(&g24[s * 10 + ll]);
                float2 a = __half22float2(*(__half2*)&p.x);
                float2 b = __half22float2(*(__half2*)&p.y);
                acc.x += e * a.x; acc.y += e * a.y;
                acc.z += e * b.x; acc.w += e * b.y;
            }
        }
    }
    const float rinv = 1.f / (den + EPSV);

    float4 v = make_float4(-1e30f, -1e30f, -1e30f, -1e30f);
    if (act) {
        v = ((const float4*)b2)[ll];
        v.x += acc.x * rinv; v.y += acc.y * rinv;
        v.z += acc.z * rinv; v.w += acc.w * rinv;
    }
    float mx = act ? fmaxf(fmaxf(v.x, v.y), fmaxf(v.z, v.w)) : -1e30f;
    #pragma unroll
    for (int o = 8; o; o >>= 1) mx = fmaxf(mx, __shfl_xor_sync(FULL, mx, o));
    float sm = 0.f;
    if (act) sm = __expf(v.x - mx) + __expf(v.y - mx) + __expf(v.z - mx) + __expf(v.w - mx);
    #pragma unroll
    for (int o = 8; o; o >>= 1) sm += __shfl_xor_sync(FULL, sm, o);
    float lse = mx + logf(sm);
    if (act)
        ((float4*)out)[n * 10 + ll] =
            make_float4(v.x - lse, v.y - lse, v.z - lse, v.w - lse);
}

// ---------------- launch ----------------
extern "C" void kernel_launch(void* const* d_in, const int* in_sizes, int n_in,
                              void* d_out, int out_size)
{
    const float* x      = (const float*)d_in[0];
    const int*   eidx   = (const int*)d_in[1];
    const float* W1     = (const float*)d_in[2];
    const float* a_src1 = (const float*)d_in[3];
    const float* a_dst1 = (const float*)d_in[4];
    const float* b1     = (const float*)d_in[5];
    const float* W2     = (const float*)d_in[6];
    const float* a_src2 = (const float*)d_in[7];
    const float* a_dst2 = (const float*)d_in[8];
    const float* b2     = (const float*)d_in[9];
    const int* src = eidx;
    const int* dst = eidx + EE;
    float* out = (float*)d_out;

    // Side stream + events for fork/join overlap of the CSR build with gemm1.
    static cudaStream_t sB = nullptr;
    static cudaEvent_t evFork = nullptr, evJoin = nullptr;
    if (sB == nullptr) {
        cudaStreamCreateWithFlags(&sB, cudaStreamNonBlocking);
        cudaEventCreateWithFlags(&evFork, cudaEventDisableTiming);
        cudaEventCreateWithFlags(&evJoin, cudaEventDisableTiming);
    }

    const int G1_SMEM = (64 * 128 + 64 * 128) * 4;   // 64 KB
    (void)cudaFuncSetAttribute(gemm1_kernel,
                               cudaFuncAttributeMaxDynamicSharedMemorySize, G1_SMEM);

    // fork: sort chain on sB runs concurrently with gemm1 on the main stream
    cudaEventRecord(evFork, 0);
    cudaStreamWaitEvent(sB, evFork, 0);

    gemm1_kernel<<<(NN + 63) / 64, 256, G1_SMEM>>>(x, W1, a_src1, a_dst1); // main
    hist_kernel<<<(EE / 4 + 255) / 256, 256, 0, sB>>>(dst);
    scan1_kernel<<<98, 1024, 0, sB>>>();
    scanB_kernel<<<98, 1024, 0, sB>>>();
    scatter_kernel<<<(EE / 4 + 255) / 256, 256, 0, sB>>>(src, dst);

    // join: agg1 needs both gemm1 outputs and the CSR
    cudaEventRecord(evJoin, sB);
    cudaStreamWaitEvent(0, evJoin, 0);

    agg1_kernel<<<NN / 8, 256>>>(b1);
    gemm2_kernel<<<(NN + 255) / 256, 256>>>(W2, a_src2, a_dst2);
    agg2_kernel<<<NN / 16, 256>>>(b2, out);
}

// round 16
// speedup vs baseline: 1.0070x; 1.0070x over previous
#include <cuda_runtime.h>
#include <cuda_fp16.h>
#include <math.h>

#define NN 100000
#define EE 1600000
#define EPSV 1e-16f
#define NEG_SLOPE 0.2f
#define FULL 0xffffffffu

// ---------------- scratch (device globals; allocation-free) ----------------
__device__ uint4   g_h1h[NN * 16];     // h1 [N,128] fp16       25.6 MB (16B-aligned)
__device__ float   g_as1[NN * 8];      // alpha_src1 [N,8]       3.2 MB
__device__ float   g_ad1[NN * 8];      // alpha_dst1 [N,8]       3.2 MB
__device__ uint4   g_out1h[NN * 16];   // elu(out1) [N,128] fp16 25.6 MB
__device__ __half2 g_g2h[NN * 20];     // g2 [N,40] fp16           8 MB
__device__ float   g_as2[NN];          // alpha_src2 [N]
__device__ float   g_ad2[NN];          // alpha_dst2 [N]
// CSR sort scratch (g_deg self-cleans: hist fills, scatter drains to 0)
__device__ int     g_deg[NN];
__device__ int     g_off[NN + 1];
__device__ int     g_ssrc[EE];         // src sorted by dst      6.4 MB
__device__ int     g_bsum[128];

// ---------------- helpers ----------------
__device__ __forceinline__ void fma4(float4& a, float s, float4 b) {
    a.x += s * b.x; a.y += s * b.y; a.z += s * b.z; a.w += s * b.w;
}
__device__ __forceinline__ float dot4(float4 a, float4 b) {
    return a.x * b.x + a.y * b.y + a.z * b.z + a.w * b.w;
}
__device__ __forceinline__ float leaky_exp(float e) {
    float t = e > 0.f ? e : NEG_SLOPE * e;
    return __expf(t);
}
__device__ __forceinline__ uint2 pack_half4(float4 v) {
    __half2 p0 = __floats2half2_rn(v.x, v.y);
    __half2 p1 = __floats2half2_rn(v.z, v.w);
    return make_uint2(*(unsigned*)&p0, *(unsigned*)&p1);
}
// ---- packed fp32x2 (Blackwell FFMA2) ----
__device__ __forceinline__ unsigned long long pk2(float lo, float hi) {
    unsigned long long r;
    asm("mov.b64 %0, {%1, %2};" : "=l"(r) : "f"(lo), "f"(hi));
    return r;
}
__device__ __forceinline__ unsigned long long fma2(
    unsigned long long a, unsigned long long b, unsigned long long c) {
    unsigned long long d;
    asm("fma.rn.f32x2 %0, %1, %2, %3;" : "=l"(d) : "l"(a), "l"(b), "l"(c));
    return d;
}
__device__ __forceinline__ float2 upk2(unsigned long long v) {
    float2 f;
    asm("mov.b64 {%0, %1}, %2;" : "=f"(f.x), "=f"(f.y) : "l"(v));
    return f;
}

// ---------------- S1. histogram of dst (4 edges/thread) ----------------
__global__ __launch_bounds__(256) void hist_kernel(const int* __restrict__ dst) {
    int i = blockIdx.x * 256 + threadIdx.x;
    if (i < EE / 4) {
        int4 d = __ldcs(&((const int4*)dst)[i]);
        atomicAdd(&g_deg[d.x], 1);
        atomicAdd(&g_deg[d.y], 1);
        atomicAdd(&g_deg[d.z], 1);
        atomicAdd(&g_deg[d.w], 1);
    }
}

// ---------------- S2a. block-level exclusive scan of degrees ----------------
__global__ __launch_bounds__(1024) void scan1_kernel() {
    int t = threadIdx.x;
    int i = blockIdx.x * 1024 + t;
    int v = (i < NN) ? g_deg[i] : 0;
    int lane = t & 31, w = t >> 5;
    int x = v;
    #pragma unroll
    for (int o = 1; o < 32; o <<= 1) {
        int y = __shfl_up_sync(FULL, x, o);
        if (lane >= o) x += y;
    }
    __shared__ int wt[32];
    if (lane == 31) wt[w] = x;
    __syncthreads();
    if (w == 0) {
        int z = wt[lane];
        #pragma unroll
        for (int o = 1; o < 32; o <<= 1) {
            int y = __shfl_up_sync(FULL, z, o);
            if (lane >= o) z += y;
        }
        wt[lane] = z;
    }
    __syncthreads();
    int pre = (w ? wt[w - 1] : 0);
    if (i < NN) g_off[i] = pre + x - v;      // block-local exclusive
    if (t == 1023) g_bsum[blockIdx.x] = wt[31];
}

// ---------------- S2b. add block prefix ----------------
__global__ __launch_bounds__(1024) void scanB_kernel() {
    __shared__ int s[128];
    __shared__ int blockpre;
    int t = threadIdx.x;
    if (t < 128) s[t] = (t < 98) ? g_bsum[t] : 0;
    __syncthreads();
    if (t == 0) {
        int run = 0;
        for (int b = 0; b < blockIdx.x; b++) run += s[b];
        blockpre = run;
    }
    __syncthreads();
    int i = blockIdx.x * 1024 + t;
    if (i < NN) g_off[i] += blockpre;
    if (i == 0) g_off[NN] = EE;
}

// ---------------- S3. scatter (4 edges/thread; drains g_deg to 0) -----------
__global__ __launch_bounds__(256) void scatter_kernel(
    const int* __restrict__ src, const int* __restrict__ dst)
{
    int i = blockIdx.x * 256 + threadIdx.x;
    if (i < EE / 4) {
        int4 d = __ldcs(&((const int4*)dst)[i]);
        int4 s = __ldcs(&((const int4*)src)[i]);
        int p0 = g_off[d.x] + atomicSub(&g_deg[d.x], 1) - 1;
        int p1 = g_off[d.y] + atomicSub(&g_deg[d.y], 1) - 1;
        int p2 = g_off[d.z] + atomicSub(&g_deg[d.z], 1) - 1;
        int p3 = g_off[d.w] + atomicSub(&g_deg[d.w], 1) - 1;
        __stcs(&g_ssrc[p0], s.x);
        __stcs(&g_ssrc[p1], s.y);
        __stcs(&g_ssrc[p2], s.z);
        __stcs(&g_ssrc[p3], s.w);
    }
}

// ---------------- 1. GEMM1 (register-tiled, f32x2): h1(fp16)=x@W1 -----------
__global__ __launch_bounds__(256) void gemm1_kernel(
    const float* __restrict__ x, const float* __restrict__ W1,
    const float* __restrict__ a_src, const float* __restrict__ a_dst)
{
    extern __shared__ float smem[];
    float4* sW4 = (float4*)smem;                 // [k*32 + c4] (64 k-rows)
    float4* sx4 = (float4*)(smem + 64 * 128);    // [n*32 + k4]
    const ulonglong2* sW2 = (const ulonglong2*)smem;
    const int tid = threadIdx.x;
    const int cx = tid & 31;      // col quad
    const int ny = tid >> 5;      // node group of 8
    const int nbase = blockIdx.x * 64;
    const float4* W4 = (const float4*)W1;
    const float4* x4 = (const float4*)x;

    #pragma unroll
    for (int it = 0; it < 8; it++) {             // x: 2048 f4
        int f = tid + it * 256;
        int gn = nbase + (f >> 5);
        sx4[f] = (gn < NN) ? x4[(size_t)gn * 32 + (f & 31)]
                           : make_float4(0.f, 0.f, 0.f, 0.f);
    }

    unsigned long long c2[8][2];
    #pragma unroll
    for (int i = 0; i < 8; i++) { c2[i][0] = 0ull; c2[i][1] = 0ull; }

    #pragma unroll
    for (int ch = 0; ch < 2; ch++) {
        if (ch) __syncthreads();                 // drain reads of prev sW
        #pragma unroll
        for (int it = 0; it < 8; it++) {         // W chunk: 2048 f4
            int f = tid + it * 256;
            sW4[f] = W4[(ch * 64 + (f >> 5)) * 32 + (f & 31)];
        }
        __syncthreads();
        #pragma unroll 4
        for (int k = 0; k < 64; k += 4) {
            ulonglong2 w0 = sW2[(k + 0) * 32 + cx];
            ulonglong2 w1 = sW2[(k + 1) * 32 + cx];
            ulonglong2 w2 = sW2[(k + 2) * 32 + cx];
            ulonglong2 w3 = sW2[(k + 3) * 32 + cx];
            #pragma unroll
            for (int i = 0; i < 8; i++) {
                float4 xv = sx4[(ny * 8 + i) * 32 + ((ch * 64 + k) >> 2)];
                unsigned long long d0 = pk2(xv.x, xv.x);
                unsigned long long d1 = pk2(xv.y, xv.y);
                unsigned long long d2 = pk2(xv.z, xv.z);
                unsigned long long d3 = pk2(xv.w, xv.w);
                c2[i][0] = fma2(d0, w0.x, c2[i][0]);
                c2[i][1] = fma2(d0, w0.y, c2[i][1]);
                c2[i][0] = fma2(d1, w1.x, c2[i][0]);
                c2[i][1] = fma2(d1, w1.y, c2[i][1]);
                c2[i][0] = fma2(d2, w2.x, c2[i][0]);
                c2[i][1] = fma2(d2, w2.y, c2[i][1]);
                c2[i][0] = fma2(d3, w3.x, c2[i][0]);
                c2[i][1] = fma2(d3, w3.y, c2[i][1]);
            }
        }
    }

    // epilogue: unpack, store h1 (fp16) + per-head alpha dots
    const int head = cx >> 2, cq = cx & 3;
    const float4 asv = ((const float4*)a_src)[head * 4 + cq];
    const float4 adv = ((const float4*)a_dst)[head * 4 + cq];
    #pragma unroll
    for (int i = 0; i < 8; i++) {
        int gn = nbase + ny * 8 + i;
        float2 lo = upk2(c2[i][0]);
        float2 hi = upk2(c2[i][1]);
        float4 ci = make_float4(lo.x, lo.y, hi.x, hi.y);
        float ps = dot4(ci, asv);
        float pd = dot4(ci, adv);
        ps += __shfl_xor_sync(FULL, ps, 1); ps += __shfl_xor_sync(FULL, ps, 2);
        pd += __shfl_xor_sync(FULL, pd, 1); pd += __shfl_xor_sync(FULL, pd, 2);
        if (gn < NN) {
            ((uint2*)g_h1h)[gn * 32 + cx] = pack_half4(ci);
            if (cq == 0) { g_as1[gn * 8 + head] = ps; g_ad1[gn * 8 + head] = pd; }
        }
    }
}

// ---------------- 2. L1 aggregate: warp/node, 8 edges in flight -------------
__global__ __launch_bounds__(256) void agg1_kernel(const float* __restrict__ b1)
{
    const int n = (blockIdx.x * 256 + threadIdx.x) >> 5;   // node (grid exact)
    const int l = threadIdx.x & 31;
    const int half = l >> 4;       // which edge of the pair
    const int ll = l & 15;         // channel-group lane (8 channels)
    const int headl = ll >> 1;     // head of channels ll*8..ll*8+7
    const int beg = g_off[n], end = g_off[n + 1];
    const float adp = g_ad1[n * 8 + headl];

    float den = 0.f;
    float a0=0.f,a1=0.f,a2=0.f,a3=0.f,a4=0.f,a5=0.f,a6=0.f,a7=0.f;

    for (int base = beg; base < end; base += 32) {
        const int je = min(32, end - base);
        const int sj = (l < je) ? __ldg(&g_ssrc[base + l]) : 0;
        const int nst = (je + 1) >> 1;
        int i = 0;
        #pragma unroll 1
        for (; i + 4 <= nst; i += 4) {
            int e0i = 2 * i + half, e1i = e0i + 2, e2i = e0i + 4, e3i = e0i + 6;
            int s0 = __shfl_sync(FULL, sj, e0i);
            int s1 = __shfl_sync(FULL, sj, e1i);
            int s2 = __shfl_sync(FULL, sj, e2i);
            int s3 = __shfl_sync(FULL, sj, e3i);
            float x0 = leaky_exp(__ldg(&g_as1[s0 * 8 + headl]) + adp);
            float x1 = leaky_exp(__ldg(&g_as1[s1 * 8 + headl]) + adp);
            float x2 = leaky_exp(__ldg(&g_as1[s2 * 8 + headl]) + adp);
            float x3 = leaky_exp(__ldg(&g_as1[s3 * 8 + headl]) + adp);
            x0 = (e0i < je) ? x0 : 0.f;
            x1 = (e1i < je) ? x1 : 0.f;
            x2 = (e2i < je) ? x2 : 0.f;
            x3 = (e3i < je) ? x3 : 0.f;
            uint4 p0 = __ldg(&g_h1h[s0 * 16 + ll]);
            uint4 p1 = __ldg(&g_h1h[s1 * 16 + ll]);
            uint4 p2 = __ldg(&g_h1h[s2 * 16 + ll]);
            uint4 p3 = __ldg(&g_h1h[s3 * 16 + ll]);
            den += (x0 + x1) + (x2 + x3);
            float2 q;
            q = __half22float2(*(__half2*)&p0.x); a0 += x0*q.x; a1 += x0*q.y;
            q = __half22float2(*(__half2*)&p0.y); a2 += x0*q.x; a3 += x0*q.y;
            q = __half22float2(*(__half2*)&p0.z); a4 += x0*q.x; a5 += x0*q.y;
            q = __half22float2(*(__half2*)&p0.w); a6 += x0*q.x; a7 += x0*q.y;
            q = __half22float2(*(__half2*)&p1.x); a0 += x1*q.x; a1 += x1*q.y;
            q = __half22float2(*(__half2*)&p1.y); a2 += x1*q.x; a3 += x1*q.y;
            q = __half22float2(*(__half2*)&p1.z); a4 += x1*q.x; a5 += x1*q.y;
            q = __half22float2(*(__half2*)&p1.w); a6 += x1*q.x; a7 += x1*q.y;
            q = __half22float2(*(__half2*)&p2.x); a0 += x2*q.x; a1 += x2*q.y;
            q = __half22float2(*(__half2*)&p2.y); a2 += x2*q.x; a3 += x2*q.y;
            q = __half22float2(*(__half2*)&p2.z); a4 += x2*q.x; a5 += x2*q.y;
            q = __half22float2(*(__half2*)&p2.w); a6 += x2*q.x; a7 += x2*q.y;
            q = __half22float2(*(__half2*)&p3.x); a0 += x3*q.x; a1 += x3*q.y;
            q = __half22float2(*(__half2*)&p3.y); a2 += x3*q.x; a3 += x3*q.y;
            q = __half22float2(*(__half2*)&p3.z); a4 += x3*q.x; a5 += x3*q.y;
            q = __half22float2(*(__half2*)&p3.w); a6 += x3*q.x; a7 += x3*q.y;
        }
        #pragma unroll 1
        for (; i < nst; i++) {
            int ei = 2 * i + half;
            int s = __shfl_sync(FULL, sj, ei);
            float e = leaky_exp(__ldg(&g_as1[s * 8 + headl]) + adp);
            e = (ei < je) ? e : 0.f;
            uint4 p = __ldg(&g_h1h[s * 16 + ll]);
            den += e;
            float2 q;
            q = __half22float2(*(__half2*)&p.x); a0 += e*q.x; a1 += e*q.y;
            q = __half22float2(*(__half2*)&p.y); a2 += e*q.x; a3 += e*q.y;
            q = __half22float2(*(__half2*)&p.z); a4 += e*q.x; a5 += e*q.y;
            q = __half22float2(*(__half2*)&p.w); a6 += e*q.x; a7 += e*q.y;
        }
    }
    // combine halves (all lanes converged)
    a0 += __shfl_xor_sync(FULL, a0, 16); a1 += __shfl_xor_sync(FULL, a1, 16);
    a2 += __shfl_xor_sync(FULL, a2, 16); a3 += __shfl_xor_sync(FULL, a3, 16);
    a4 += __shfl_xor_sync(FULL, a4, 16); a5 += __shfl_xor_sync(FULL, a5, 16);
    a6 += __shfl_xor_sync(FULL, a6, 16); a7 += __shfl_xor_sync(FULL, a7, 16);
    den += __shfl_xor_sync(FULL, den, 16);

    const float rinv = 1.f / (den + EPSV);
    const float4* b14 = (const float4*)b1;
    float4 bA = b14[ll * 2], bB = b14[ll * 2 + 1];
    float v0 = bA.x + a0 * rinv, v1 = bA.y + a1 * rinv;
    float v2 = bA.z + a2 * rinv, v3 = bA.w + a3 * rinv;
    float v4 = bB.x + a4 * rinv, v5 = bB.y + a5 * rinv;
    float v6 = bB.z + a6 * rinv, v7 = bB.w + a7 * rinv;
    v0 = v0 > 0.f ? v0 : __expf(v0) - 1.f;
    v1 = v1 > 0.f ? v1 : __expf(v1) - 1.f;
    v2 = v2 > 0.f ? v2 : __expf(v2) - 1.f;
    v3 = v3 > 0.f ? v3 : __expf(v3) - 1.f;
    v4 = v4 > 0.f ? v4 : __expf(v4) - 1.f;
    v5 = v5 > 0.f ? v5 : __expf(v5) - 1.f;
    v6 = v6 > 0.f ? v6 : __expf(v6) - 1.f;
    v7 = v7 > 0.f ? v7 : __expf(v7) - 1.f;
    if (half == 0) {
        uint4 o;
        __half2 t0 = __floats2half2_rn(v0, v1); o.x = *(unsigned*)&t0;
        __half2 t1 = __floats2half2_rn(v2, v3); o.y = *(unsigned*)&t1;
        __half2 t2 = __floats2half2_rn(v4, v5); o.z = *(unsigned*)&t2;
        __half2 t3 = __floats2half2_rn(v6, v7); o.w = *(unsigned*)&t3;
        g_out1h[n * 16 + ll] = o;
    }
}

// ---------------- 3. GEMM2 (f32x2, double-buffered): g2(fp16) ---------------
__global__ __launch_bounds__(256) void gemm2_kernel(
    const float* __restrict__ W2, const float* __restrict__ a_src,
    const float* __restrict__ a_dst)
{
    __shared__ float4 sW[128 * 10];
    __shared__ float4 sas[10], sad[10];
    __shared__ float  sx[256 * 17];
    const int tid = threadIdx.x;
    const int node = blockIdx.x * 256 + tid;
    const float4* W4 = (const float4*)W2;
    const ulonglong2* sW2p = (const ulonglong2*)sW;
    #pragma unroll
    for (int it = 0; it < 5; it++) sW[tid + it * 256] = W4[tid + it * 256];
    if (tid < 10) { sas[tid] = ((const float4*)a_src)[tid];
                    sad[tid] = ((const float4*)a_dst)[tid]; }
    const unsigned* hinw = (const unsigned*)g_out1h;   // raw half2 words

    unsigned long long acc2[10][2];
    #pragma unroll
    for (int j = 0; j < 10; j++) { acc2[j][0] = 0ull; acc2[j][1] = 0ull; }

    unsigned buf[8];
    #pragma unroll
    for (int it = 0; it < 8; it++) {
        int f = tid + it * 256;
        int nl2 = f >> 3, kp = f & 7;
        int gn = blockIdx.x * 256 + nl2;
        buf[it] = (gn < NN) ? __ldg(&hinw[(size_t)gn * 64 + kp]) : 0u;
    }

    for (int kc = 0; kc < 8; kc++) {
        __syncthreads();
        #pragma unroll
        for (int it = 0; it < 8; it++) {             // store current chunk
            int f = tid + it * 256;
            int nl2 = f >> 3, kp = f & 7;
            float2 fv = __half22float2(*(__half2*)&buf[it]);
            sx[nl2 * 17 + kp * 2 + 0] = fv.x;
            sx[nl2 * 17 + kp * 2 + 1] = fv.y;
        }
        if (kc < 7) {                                // prefetch next chunk
            #pragma unroll
            for (int it = 0; it < 8; it++) {
                int f = tid + it * 256;
                int nl2 = f >> 3, kp = f & 7;
                int gn = blockIdx.x * 256 + nl2;
                buf[it] = (gn < NN)
                    ? __ldg(&hinw[(size_t)gn * 64 + (kc + 1) * 8 + kp]) : 0u;
            }
        }
        __syncthreads();
        #pragma unroll
        for (int k = 0; k < 16; k++) {
            float xv = sx[tid * 17 + k];
            unsigned long long xd = pk2(xv, xv);
            const ulonglong2* wr = &sW2p[(kc * 16 + k) * 10];
            #pragma unroll
            for (int j = 0; j < 10; j++) {
                ulonglong2 w = wr[j];
                acc2[j][0] = fma2(xd, w.x, acc2[j][0]);
                acc2[j][1] = fma2(xd, w.y, acc2[j][1]);
            }
        }
    }
    if (node < NN) {
        float s = 0.f, d = 0.f;
        float4 accf[10];
        #pragma unroll
        for (int j = 0; j < 10; j++) {
            float2 lo = upk2(acc2[j][0]);
            float2 hi = upk2(acc2[j][1]);
            accf[j] = make_float4(lo.x, lo.y, hi.x, hi.y);
            s += dot4(accf[j], sas[j]);
            d += dot4(accf[j], sad[j]);
        }
        #pragma unroll
        for (int j = 0; j < 10; j++)
            *(uint2*)&g_g2h[node * 20 + 2 * j] = pack_half4(accf[j]);
        g_as2[node] = s;
        g_ad2[node] = d;
    }
}

// ---------------- 4. L2 aggregate: THREE nodes per warp (10 lanes each) -----
// Divergence-free: fixed 10-step inner loop, e=0 select for invalid edges,
// warp-wide max trip count -> all shuffles FULL-mask legal by construction.
__global__ __launch_bounds__(256) void agg2_kernel(
    const float* __restrict__ b2, float* __restrict__ out)
{
    const int w = (blockIdx.x * 256 + threadIdx.x) >> 5;   // warp id
    const int l = threadIdx.x & 31;
    const int g = (l < 10) ? 0 : ((l < 20) ? 1 : 2);
    const int gl = l - g * 10;         // 0..9 (lanes 30,31 -> 10,11)
    const int gbase = g * 10;
    int n = 3 * w + g;
    const bool act = (n < NN) && (gl < 10);
    n = min(n, NN - 1);
    const int beg = g_off[n], end = g_off[n + 1];
    const float ad2n = g_ad2[n];
    const uint2* g24 = (const uint2*)g_g2h;      // [n*10 + c] -> 4 halves

    float den = 0.f;
    float4 acc = make_float4(0.f, 0.f, 0.f, 0.f);

    int nIter = (end - beg + 9) / 10;
    #pragma unroll
    for (int o = 16; o; o >>= 1)
        nIter = max(nIter, __shfl_xor_sync(FULL, nIter, o));

    for (int it = 0; it < nIter; it++) {
        const int base = beg + it * 10;
        const int sj = (gl < 10 && base + gl < end)
                     ? __ldg(&g_ssrc[base + gl]) : 0;
        #pragma unroll
        for (int k = 0; k < 10; k++) {
            int s = __shfl_sync(FULL, sj, gbase + k);
            bool val = (base + k < end);
            float e = leaky_exp(__ldg(&g_as2[s]) + ad2n);
            e = val ? e : 0.f;
            den += e;
            if (act && val) {
                uint2 p = __ldg(&g24[s * 10 + gl]);
                float2 a = __half22float2(*(__half2*)&p.x);
                float2 b = __half22float2(*(__half2*)&p.y);
                acc.x += e * a.x; acc.y += e * a.y;
                acc.z += e * b.x; acc.w += e * b.y;
            }
        }
    }
    const float rinv = 1.f / (den + EPSV);

    float4 v = make_float4(-1e30f, -1e30f, -1e30f, -1e30f);
    if (act) {
        v = ((const float4*)b2)[gl];
        v.x += acc.x * rinv; v.y += acc.y * rinv;
        v.z += acc.z * rinv; v.w += acc.w * rinv;
    }
    // group max: circular doubling over 10 lanes (idempotent -> overlap OK)
    float mx = act ? fmaxf(fmaxf(v.x, v.y), fmaxf(v.z, v.w)) : -1e30f;
    #pragma unroll
    for (int o = 1; o < 16; o <<= 1) {
        int srcl = gbase + ((gl + o) % 10);
        mx = fmaxf(mx, __shfl_sync(FULL, mx, srcl));
    }
    float sm = 0.f;
    if (act) sm = __expf(v.x - mx) + __expf(v.y - mx) + __expf(v.z - mx) + __expf(v.w - mx);
    // group sum: exact 9-step ring over the 10 lanes
    float tot = sm;
    #pragma unroll
    for (int i = 1; i < 10; i++) {
        int srcl = gbase + ((gl + i) % 10);
        tot += __shfl_sync(FULL, sm, srcl);
    }
    float lse = mx + logf(tot);
    if (act)
        ((float4*)out)[n * 10 + gl] =
            make_float4(v.x - lse, v.y - lse, v.z - lse, v.w - lse);
}

// ---------------- launch ----------------
extern "C" void kernel_launch(void* const* d_in, const int* in_sizes, int n_in,
                              void* d_out, int out_size)
{
    const float* x      = (const float*)d_in[0];
    const int*   eidx   = (const int*)d_in[1];
    const float* W1     = (const float*)d_in[2];
    const float* a_src1 = (const float*)d_in[3];
    const float* a_dst1 = (const float*)d_in[4];
    const float* b1     = (const float*)d_in[5];
    const float* W2     = (const float*)d_in[6];
    const float* a_src2 = (const float*)d_in[7];
    const float* a_dst2 = (const float*)d_in[8];
    const float* b2     = (const float*)d_in[9];
    const int* src = eidx;
    const int* dst = eidx + EE;
    float* out = (float*)d_out;

    // Side stream + events for fork/join overlap of the CSR build with gemm1.
    static cudaStream_t sB = nullptr;
    static cudaEvent_t evFork = nullptr, evJoin = nullptr;
    if (sB == nullptr) {
        cudaStreamCreateWithFlags(&sB, cudaStreamNonBlocking);
        cudaEventCreateWithFlags(&evFork, cudaEventDisableTiming);
        cudaEventCreateWithFlags(&evJoin, cudaEventDisableTiming);
    }

    const int G1_SMEM = (64 * 128 + 64 * 128) * 4;   // 64 KB
    (void)cudaFuncSetAttribute(gemm1_kernel,
                               cudaFuncAttributeMaxDynamicSharedMemorySize, G1_SMEM);

    // fork: sort chain on sB runs concurrently with gemm1 on the main stream.
    // Submission order puts gemm1 4th so ncu's capture slot profiles it.
    cudaEventRecord(evFork, 0);
    cudaStreamWaitEvent(sB, evFork, 0);

    hist_kernel<<<(EE / 4 + 255) / 256, 256, 0, sB>>>(dst);                // 1
    scan1_kernel<<<98, 1024, 0, sB>>>();                                   // 2
    scanB_kernel<<<98, 1024, 0, sB>>>();                                   // 3
    gemm1_kernel<<<(NN + 63) / 64, 256, G1_SMEM>>>(x, W1, a_src1, a_dst1); // 4 (ncu)
    scatter_kernel<<<(EE / 4 + 255) / 256, 256, 0, sB>>>(src, dst);        // 5

    // join: agg1 needs both gemm1 outputs and the CSR
    cudaEventRecord(evJoin, sB);
    cudaStreamWaitEvent(0, evJoin, 0);

    agg1_kernel<<<NN / 8, 256>>>(b1);                                      // 6
    gemm2_kernel<<<(NN + 255) / 256, 256>>>(W2, a_src2, a_dst2);           // 7
    agg2_kernel<<<(NN / 3 + 8) / 8 + 1, 256>>>(b2, out);                   // 8
}

// round 17
// speedup vs baseline: 1.2029x; 1.1945x over previous
#include <cuda_runtime.h>
#include <cuda_fp16.h>
#include <math.h>

#define NN 100000
#define EE 1600000
#define EPSV 1e-16f
#define NEG_SLOPE 0.2f
#define FULL 0xffffffffu

// ---------------- scratch (device globals; allocation-free) ----------------
__device__ uint4   g_h1h[NN * 16];     // h1 [N,128] fp16       25.6 MB (16B-aligned)
__device__ float   g_as1[NN * 8];      // alpha_src1 [N,8]       3.2 MB
__device__ float   g_ad1[NN * 8];      // alpha_dst1 [N,8]       3.2 MB
__device__ uint4   g_out1h[NN * 16];   // elu(out1) [N,128] fp16 25.6 MB
__device__ __half2 g_g2h[NN * 20];     // g2 [N,40] fp16           8 MB
__device__ float   g_as2[NN];          // alpha_src2 [N]
__device__ float   g_ad2[NN];          // alpha_dst2 [N]
// CSR sort scratch (g_deg self-cleans: hist fills, scatter drains to 0)
__device__ int     g_deg[NN];
__device__ int     g_off[NN + 1];
__device__ int     g_ssrc[EE];         // src sorted by dst      6.4 MB
__device__ int     g_bsum[128];

// ---------------- helpers ----------------
__device__ __forceinline__ float dot4(float4 a, float4 b) {
    return a.x * b.x + a.y * b.y + a.z * b.z + a.w * b.w;
}
__device__ __forceinline__ float leaky_exp(float e) {
    float t = e > 0.f ? e : NEG_SLOPE * e;
    return __expf(t);
}
__device__ __forceinline__ uint2 pack_half4(float4 v) {
    __half2 p0 = __floats2half2_rn(v.x, v.y);
    __half2 p1 = __floats2half2_rn(v.z, v.w);
    return make_uint2(*(unsigned*)&p0, *(unsigned*)&p1);
}
// ---- packed fp32x2 (used by gemm2) ----
__device__ __forceinline__ unsigned long long pk2(float lo, float hi) {
    unsigned long long r;
    asm("mov.b64 %0, {%1, %2};" : "=l"(r) : "f"(lo), "f"(hi));
    return r;
}
__device__ __forceinline__ unsigned long long fma2(
    unsigned long long a, unsigned long long b, unsigned long long c) {
    unsigned long long d;
    asm("fma.rn.f32x2 %0, %1, %2, %3;" : "=l"(d) : "l"(a), "l"(b), "l"(c));
    return d;
}
__device__ __forceinline__ float2 upk2(unsigned long long v) {
    float2 f;
    asm("mov.b64 {%0, %1}, %2;" : "=f"(f.x), "=f"(f.y) : "l"(v));
    return f;
}

// ---------------- S1. histogram of dst (4 edges/thread) ----------------
__global__ __launch_bounds__(256) void hist_kernel(const int* __restrict__ dst) {
    int i = blockIdx.x * 256 + threadIdx.x;
    if (i < EE / 4) {
        int4 d = __ldcs(&((const int4*)dst)[i]);
        atomicAdd(&g_deg[d.x], 1);
        atomicAdd(&g_deg[d.y], 1);
        atomicAdd(&g_deg[d.z], 1);
        atomicAdd(&g_deg[d.w], 1);
    }
}

// ---------------- S2a. block-level exclusive scan of degrees ----------------
__global__ __launch_bounds__(1024) void scan1_kernel() {
    int t = threadIdx.x;
    int i = blockIdx.x * 1024 + t;
    int v = (i < NN) ? g_deg[i] : 0;
    int lane = t & 31, w = t >> 5;
    int x = v;
    #pragma unroll
    for (int o = 1; o < 32; o <<= 1) {
        int y = __shfl_up_sync(FULL, x, o);
        if (lane >= o) x += y;
    }
    __shared__ int wt[32];
    if (lane == 31) wt[w] = x;
    __syncthreads();
    if (w == 0) {
        int z = wt[lane];
        #pragma unroll
        for (int o = 1; o < 32; o <<= 1) {
            int y = __shfl_up_sync(FULL, z, o);
            if (lane >= o) z += y;
        }
        wt[lane] = z;
    }
    __syncthreads();
    int pre = (w ? wt[w - 1] : 0);
    if (i < NN) g_off[i] = pre + x - v;      // block-local exclusive
    if (t == 1023) g_bsum[blockIdx.x] = wt[31];
}

// ---------------- S2b. add block prefix ----------------
__global__ __launch_bounds__(1024) void scanB_kernel() {
    __shared__ int s[128];
    __shared__ int blockpre;
    int t = threadIdx.x;
    if (t < 128) s[t] = (t < 98) ? g_bsum[t] : 0;
    __syncthreads();
    if (t == 0) {
        int run = 0;
        for (int b = 0; b < blockIdx.x; b++) run += s[b];
        blockpre = run;
    }
    __syncthreads();
    int i = blockIdx.x * 1024 + t;
    if (i < NN) g_off[i] += blockpre;
    if (i == 0) g_off[NN] = EE;
}

// ---------------- S3. scatter (4 edges/thread; drains g_deg to 0) -----------
__global__ __launch_bounds__(256) void scatter_kernel(
    const int* __restrict__ src, const int* __restrict__ dst)
{
    int i = blockIdx.x * 256 + threadIdx.x;
    if (i < EE / 4) {
        int4 d = __ldcs(&((const int4*)dst)[i]);
        int4 s = __ldcs(&((const int4*)src)[i]);
        int p0 = g_off[d.x] + atomicSub(&g_deg[d.x], 1) - 1;
        int p1 = g_off[d.y] + atomicSub(&g_deg[d.y], 1) - 1;
        int p2 = g_off[d.z] + atomicSub(&g_deg[d.z], 1) - 1;
        int p3 = g_off[d.w] + atomicSub(&g_deg[d.w], 1) - 1;
        __stcs(&g_ssrc[p0], s.x);
        __stcs(&g_ssrc[p1], s.y);
        __stcs(&g_ssrc[p2], s.z);
        __stcs(&g_ssrc[p3], s.w);
    }
}

// ---------------- 1. GEMM1 (tensor-core HMMA): h1(fp16) = x@W1 + alphas -----
// Block: 128 nodes. smem: sA = x tile fp16 [128][136], sB = W1 fp16 [128][136]
// (8-half row pad -> conflict-free ldmatrix). Warp: 16 nodes x 128 cols via
// mma.m16n8k16 (8 k-steps x 16 n-tiles).
#define G1ROW 136
__global__ __launch_bounds__(256, 2) void gemm1_kernel(
    const float* __restrict__ x, const float* __restrict__ W1,
    const float* __restrict__ a_src, const float* __restrict__ a_dst)
{
    extern __shared__ __half smem[];
    __half* sA = smem;                 // x tile
    __half* sB = smem + 128 * G1ROW;   // W1
    const int tid = threadIdx.x;
    const int nbase = blockIdx.x * 128;
    const float4* x4 = (const float4*)x;
    const float4* W4 = (const float4*)W1;

    // convert x tile + W1 to fp16 in smem
    #pragma unroll
    for (int it = 0; it < 16; it++) {
        int f = tid + it * 256;          // 4096 float4
        int r = f >> 5, c4 = f & 31;
        int gn = nbase + r;
        float4 v = (gn < NN) ? x4[(size_t)gn * 32 + c4]
                             : make_float4(0.f, 0.f, 0.f, 0.f);
        __half2 h0 = __floats2half2_rn(v.x, v.y);
        __half2 h1p = __floats2half2_rn(v.z, v.w);
        *(__half2*)&sA[r * G1ROW + c4 * 4]     = h0;
        *(__half2*)&sA[r * G1ROW + c4 * 4 + 2] = h1p;
        float4 wv = W4[f];               // W1: 128x128 = 4096 f4
        __half2 w0 = __floats2half2_rn(wv.x, wv.y);
        __half2 w1 = __floats2half2_rn(wv.z, wv.w);
        *(__half2*)&sB[r * G1ROW + c4 * 4]     = w0;
        *(__half2*)&sB[r * G1ROW + c4 * 4 + 2] = w1;
    }
    __syncthreads();

    const int lane = tid & 31, wid = tid >> 5;
    const int g = lane >> 2, tg = lane & 3;
    const int wbase = wid * 16;

    // ldmatrix base addresses
    const int aRow = wbase + (lane & 15);
    const unsigned aBase = (unsigned)__cvta_generic_to_shared(
        &sA[aRow * G1ROW + ((lane >> 4) << 3)]);
    const unsigned bBase = (unsigned)__cvta_generic_to_shared(
        &sB[(lane & 15) * G1ROW]);

    float acc[16][4];
    #pragma unroll
    for (int nt = 0; nt < 16; nt++)
        acc[nt][0] = acc[nt][1] = acc[nt][2] = acc[nt][3] = 0.f;

    #pragma unroll
    for (int kk = 0; kk < 8; kk++) {
        unsigned a0, a1, a2, a3;
        asm volatile(
            "ldmatrix.sync.aligned.m8n8.x4.shared.b16 {%0,%1,%2,%3}, [%4];"
            : "=r"(a0), "=r"(a1), "=r"(a2), "=r"(a3)
            : "r"(aBase + kk * 32));                  // +16 halves per k-step
        #pragma unroll
        for (int nt = 0; nt < 16; nt++) {
            unsigned b0, b1;
            asm volatile(
                "ldmatrix.sync.aligned.m8n8.x2.trans.shared.b16 {%0,%1}, [%2];"
                : "=r"(b0), "=r"(b1)
                : "r"(bBase + (kk * 16 * G1ROW + nt * 8) * 2));
            asm volatile(
                "mma.sync.aligned.m16n8k16.row.col.f32.f16.f16.f32 "
                "{%0,%1,%2,%3}, {%4,%5,%6,%7}, {%8,%9}, {%0,%1,%2,%3};"
                : "+f"(acc[nt][0]), "+f"(acc[nt][1]),
                  "+f"(acc[nt][2]), "+f"(acc[nt][3])
                : "r"(a0), "r"(a1), "r"(a2), "r"(a3), "r"(b0), "r"(b1));
        }
    }

    // epilogue: D rows g (n0) and g+8 (n1); thread owns cols nt*8+tg*2, +1
    const int n0 = nbase + wbase + g;
    const int n1 = n0 + 8;
    unsigned* h1w = (unsigned*)g_h1h;
    #pragma unroll
    for (int nt = 0; nt < 16; nt++) {
        __half2 lo = __floats2half2_rn(acc[nt][0], acc[nt][1]);
        __half2 hi = __floats2half2_rn(acc[nt][2], acc[nt][3]);
        if (n0 < NN) h1w[(size_t)n0 * 64 + nt * 4 + tg] = *(unsigned*)&lo;
        if (n1 < NN) h1w[(size_t)n1 * 64 + nt * 4 + tg] = *(unsigned*)&hi;
    }
    const float2* as2 = (const float2*)a_src;    // flat over [8,16] channels
    const float2* ad2 = (const float2*)a_dst;
    #pragma unroll
    for (int h = 0; h < 8; h++) {
        float2 aS0 = as2[(2 * h) * 4 + tg];
        float2 aS1 = as2[(2 * h + 1) * 4 + tg];
        float2 aD0 = ad2[(2 * h) * 4 + tg];
        float2 aD1 = ad2[(2 * h + 1) * 4 + tg];
        float s0 = acc[2*h][0]*aS0.x + acc[2*h][1]*aS0.y
                 + acc[2*h+1][0]*aS1.x + acc[2*h+1][1]*aS1.y;
        float d0 = acc[2*h][0]*aD0.x + acc[2*h][1]*aD0.y
                 + acc[2*h+1][0]*aD1.x + acc[2*h+1][1]*aD1.y;
        float s1 = acc[2*h][2]*aS0.x + acc[2*h][3]*aS0.y
                 + acc[2*h+1][2]*aS1.x + acc[2*h+1][3]*aS1.y;
        float d1 = acc[2*h][2]*aD0.x + acc[2*h][3]*aD0.y
                 + acc[2*h+1][2]*aD1.x + acc[2*h+1][3]*aD1.y;
        s0 += __shfl_xor_sync(FULL, s0, 1); s0 += __shfl_xor_sync(FULL, s0, 2);
        d0 += __shfl_xor_sync(FULL, d0, 1); d0 += __shfl_xor_sync(FULL, d0, 2);
        s1 += __shfl_xor_sync(FULL, s1, 1); s1 += __shfl_xor_sync(FULL, s1, 2);
        d1 += __shfl_xor_sync(FULL, d1, 1); d1 += __shfl_xor_sync(FULL, d1, 2);
        if (tg == 0) {
            if (n0 < NN) { g_as1[n0 * 8 + h] = s0; g_ad1[n0 * 8 + h] = d0; }
            if (n1 < NN) { g_as1[n1 * 8 + h] = s1; g_ad1[n1 * 8 + h] = d1; }
        }
    }
}

// ---------------- 2. L1 aggregate: warp/node, 8 edges in flight -------------
__global__ __launch_bounds__(256) void agg1_kernel(const float* __restrict__ b1)
{
    const int n = (blockIdx.x * 256 + threadIdx.x) >> 5;   // node (grid exact)
    const int l = threadIdx.x & 31;
    const int half = l >> 4;       // which edge of the pair
    const int ll = l & 15;         // channel-group lane (8 channels)
    const int headl = ll >> 1;     // head of channels ll*8..ll*8+7
    const int beg = g_off[n], end = g_off[n + 1];
    const float adp = g_ad1[n * 8 + headl];

    float den = 0.f;
    float a0=0.f,a1=0.f,a2=0.f,a3=0.f,a4=0.f,a5=0.f,a6=0.f,a7=0.f;

    for (int base = beg; base < end; base += 32) {
        const int je = min(32, end - base);
        const int sj = (l < je) ? __ldg(&g_ssrc[base + l]) : 0;
        const int nst = (je + 1) >> 1;
        int i = 0;
        #pragma unroll 1
        for (; i + 4 <= nst; i += 4) {
            int e0i = 2 * i + half, e1i = e0i + 2, e2i = e0i + 4, e3i = e0i + 6;
            int s0 = __shfl_sync(FULL, sj, e0i);
            int s1 = __shfl_sync(FULL, sj, e1i);
            int s2 = __shfl_sync(FULL, sj, e2i);
            int s3 = __shfl_sync(FULL, sj, e3i);
            float x0 = leaky_exp(__ldg(&g_as1[s0 * 8 + headl]) + adp);
            float x1 = leaky_exp(__ldg(&g_as1[s1 * 8 + headl]) + adp);
            float x2 = leaky_exp(__ldg(&g_as1[s2 * 8 + headl]) + adp);
            float x3 = leaky_exp(__ldg(&g_as1[s3 * 8 + headl]) + adp);
            x0 = (e0i < je) ? x0 : 0.f;
            x1 = (e1i < je) ? x1 : 0.f;
            x2 = (e2i < je) ? x2 : 0.f;
            x3 = (e3i < je) ? x3 : 0.f;
            uint4 p0 = __ldg(&g_h1h[s0 * 16 + ll]);
            uint4 p1 = __ldg(&g_h1h[s1 * 16 + ll]);
            uint4 p2 = __ldg(&g_h1h[s2 * 16 + ll]);
            uint4 p3 = __ldg(&g_h1h[s3 * 16 + ll]);
            den += (x0 + x1) + (x2 + x3);
            float2 q;
            q = __half22float2(*(__half2*)&p0.x); a0 += x0*q.x; a1 += x0*q.y;
            q = __half22float2(*(__half2*)&p0.y); a2 += x0*q.x; a3 += x0*q.y;
            q = __half22float2(*(__half2*)&p0.z); a4 += x0*q.x; a5 += x0*q.y;
            q = __half22float2(*(__half2*)&p0.w); a6 += x0*q.x; a7 += x0*q.y;
            q = __half22float2(*(__half2*)&p1.x); a0 += x1*q.x; a1 += x1*q.y;
            q = __half22float2(*(__half2*)&p1.y); a2 += x1*q.x; a3 += x1*q.y;
            q = __half22float2(*(__half2*)&p1.z); a4 += x1*q.x; a5 += x1*q.y;
            q = __half22float2(*(__half2*)&p1.w); a6 += x1*q.x; a7 += x1*q.y;
            q = __half22float2(*(__half2*)&p2.x); a0 += x2*q.x; a1 += x2*q.y;
            q = __half22float2(*(__half2*)&p2.y); a2 += x2*q.x; a3 += x2*q.y;
            q = __half22float2(*(__half2*)&p2.z); a4 += x2*q.x; a5 += x2*q.y;
            q = __half22float2(*(__half2*)&p2.w); a6 += x2*q.x; a7 += x2*q.y;
            q = __half22float2(*(__half2*)&p3.x); a0 += x3*q.x; a1 += x3*q.y;
            q = __half22float2(*(__half2*)&p3.y); a2 += x3*q.x; a3 += x3*q.y;
            q = __half22float2(*(__half2*)&p3.z); a4 += x3*q.x; a5 += x3*q.y;
            q = __half22float2(*(__half2*)&p3.w); a6 += x3*q.x; a7 += x3*q.y;
        }
        #pragma unroll 1
        for (; i < nst; i++) {
            int ei = 2 * i + half;
            int s = __shfl_sync(FULL, sj, ei);
            float e = leaky_exp(__ldg(&g_as1[s * 8 + headl]) + adp);
            e = (ei < je) ? e : 0.f;
            uint4 p = __ldg(&g_h1h[s * 16 + ll]);
            den += e;
            float2 q;
            q = __half22float2(*(__half2*)&p.x); a0 += e*q.x; a1 += e*q.y;
            q = __half22float2(*(__half2*)&p.y); a2 += e*q.x; a3 += e*q.y;
            q = __half22float2(*(__half2*)&p.z); a4 += e*q.x; a5 += e*q.y;
            q = __half22float2(*(__half2*)&p.w); a6 += e*q.x; a7 += e*q.y;
        }
    }
    // combine halves (all lanes converged)
    a0 += __shfl_xor_sync(FULL, a0, 16); a1 += __shfl_xor_sync(FULL, a1, 16);
    a2 += __shfl_xor_sync(FULL, a2, 16); a3 += __shfl_xor_sync(FULL, a3, 16);
    a4 += __shfl_xor_sync(FULL, a4, 16); a5 += __shfl_xor_sync(FULL, a5, 16);
    a6 += __shfl_xor_sync(FULL, a6, 16); a7 += __shfl_xor_sync(FULL, a7, 16);
    den += __shfl_xor_sync(FULL, den, 16);

    const float rinv = 1.f / (den + EPSV);
    const float4* b14 = (const float4*)b1;
    float4 bA = b14[ll * 2], bB = b14[ll * 2 + 1];
    float v0 = bA.x + a0 * rinv, v1 = bA.y + a1 * rinv;
    float v2 = bA.z + a2 * rinv, v3 = bA.w + a3 * rinv;
    float v4 = bB.x + a4 * rinv, v5 = bB.y + a5 * rinv;
    float v6 = bB.z + a6 * rinv, v7 = bB.w + a7 * rinv;
    v0 = v0 > 0.f ? v0 : __expf(v0) - 1.f;
    v1 = v1 > 0.f ? v1 : __expf(v1) - 1.f;
    v2 = v2 > 0.f ? v2 : __expf(v2) - 1.f;
    v3 = v3 > 0.f ? v3 : __expf(v3) - 1.f;
    v4 = v4 > 0.f ? v4 : __expf(v4) - 1.f;
    v5 = v5 > 0.f ? v5 : __expf(v5) - 1.f;
    v6 = v6 > 0.f ? v6 : __expf(v6) - 1.f;
    v7 = v7 > 0.f ? v7 : __expf(v7) - 1.f;
    if (half == 0) {
        uint4 o;
        __half2 t0 = __floats2half2_rn(v0, v1); o.x = *(unsigned*)&t0;
        __half2 t1 = __floats2half2_rn(v2, v3); o.y = *(unsigned*)&t1;
        __half2 t2 = __floats2half2_rn(v4, v5); o.z = *(unsigned*)&t2;
        __half2 t3 = __floats2half2_rn(v6, v7); o.w = *(unsigned*)&t3;
        g_out1h[n * 16 + ll] = o;
    }
}

// ---------------- 3. GEMM2 (f32x2, double-buffered): g2(fp16) ---------------
__global__ __launch_bounds__(256) void gemm2_kernel(
    const float* __restrict__ W2, const float* __restrict__ a_src,
    const float* __restrict__ a_dst)
{
    __shared__ float4 sW[128 * 10];
    __shared__ float4 sas[10], sad[10];
    __shared__ float  sx[256 * 17];
    const int tid = threadIdx.x;
    const int node = blockIdx.x * 256 + tid;
    const float4* W4 = (const float4*)W2;
    const ulonglong2* sW2p = (const ulonglong2*)sW;
    #pragma unroll
    for (int it = 0; it < 5; it++) sW[tid + it * 256] = W4[tid + it * 256];
    if (tid < 10) { sas[tid] = ((const float4*)a_src)[tid];
                    sad[tid] = ((const float4*)a_dst)[tid]; }
    const unsigned* hinw = (const unsigned*)g_out1h;   // raw half2 words

    unsigned long long acc2[10][2];
    #pragma unroll
    for (int j = 0; j < 10; j++) { acc2[j][0] = 0ull; acc2[j][1] = 0ull; }

    unsigned buf[8];
    #pragma unroll
    for (int it = 0; it < 8; it++) {
        int f = tid + it * 256;
        int nl2 = f >> 3, kp = f & 7;
        int gn = blockIdx.x * 256 + nl2;
        buf[it] = (gn < NN) ? __ldg(&hinw[(size_t)gn * 64 + kp]) : 0u;
    }

    for (int kc = 0; kc < 8; kc++) {
        __syncthreads();
        #pragma unroll
        for (int it = 0; it < 8; it++) {             // store current chunk
            int f = tid + it * 256;
            int nl2 = f >> 3, kp = f & 7;
            float2 fv = __half22float2(*(__half2*)&buf[it]);
            sx[nl2 * 17 + kp * 2 + 0] = fv.x;
            sx[nl2 * 17 + kp * 2 + 1] = fv.y;
        }
        if (kc < 7) {                                // prefetch next chunk
            #pragma unroll
            for (int it = 0; it < 8; it++) {
                int f = tid + it * 256;
                int nl2 = f >> 3, kp = f & 7;
                int gn = blockIdx.x * 256 + nl2;
                buf[it] = (gn < NN)
                    ? __ldg(&hinw[(size_t)gn * 64 + (kc + 1) * 8 + kp]) : 0u;
            }
        }
        __syncthreads();
        #pragma unroll
        for (int k = 0; k < 16; k++) {
            float xv = sx[tid * 17 + k];
            unsigned long long xd = pk2(xv, xv);
            const ulonglong2* wr = &sW2p[(kc * 16 + k) * 10];
            #pragma unroll
            for (int j = 0; j < 10; j++) {
                ulonglong2 w = wr[j];
                acc2[j][0] = fma2(xd, w.x, acc2[j][0]);
                acc2[j][1] = fma2(xd, w.y, acc2[j][1]);
            }
        }
    }
    if (node < NN) {
        float s = 0.f, d = 0.f;
        float4 accf[10];
        #pragma unroll
        for (int j = 0; j < 10; j++) {
            float2 lo = upk2(acc2[j][0]);
            float2 hi = upk2(acc2[j][1]);
            accf[j] = make_float4(lo.x, lo.y, hi.x, hi.y);
            s += dot4(accf[j], sas[j]);
            d += dot4(accf[j], sad[j]);
        }
        #pragma unroll
        for (int j = 0; j < 10; j++)
            *(uint2*)&g_g2h[node * 20 + 2 * j] = pack_half4(accf[j]);
        g_as2[node] = s;
        g_ad2[node] = d;
    }
}

// ---------------- 4. L2 aggregate: THREE nodes per warp (10 lanes each) -----
__global__ __launch_bounds__(256) void agg2_kernel(
    const float* __restrict__ b2, float* __restrict__ out)
{
    const int w = (blockIdx.x * 256 + threadIdx.x) >> 5;   // warp id
    const int l = threadIdx.x & 31;
    const int g = (l < 10) ? 0 : ((l < 20) ? 1 : 2);
    const int gl = l - g * 10;         // 0..9 (lanes 30,31 -> 10,11)
    const int gbase = g * 10;
    int n = 3 * w + g;
    const bool act = (n < NN) && (gl < 10);
    n = min(n, NN - 1);
    const int beg = g_off[n], end = g_off[n + 1];
    const float ad2n = g_ad2[n];
    const uint2* g24 = (const uint2*)g_g2h;      // [n*10 + c] -> 4 halves

    float den = 0.f;
    float4 acc = make_float4(0.f, 0.f, 0.f, 0.f);

    int nIter = (end - beg + 9) / 10;
    #pragma unroll
    for (int o = 16; o; o >>= 1)
        nIter = max(nIter, __shfl_xor_sync(FULL, nIter, o));

    for (int it = 0; it < nIter; it++) {
        const int base = beg + it * 10;
        const int sj = (gl < 10 && base + gl < end)
                     ? __ldg(&g_ssrc[base + gl]) : 0;
        #pragma unroll
        for (int k = 0; k < 10; k++) {
            int s = __shfl_sync(FULL, sj, gbase + k);
            bool val = (base + k < end);
            float e = leaky_exp(__ldg(&g_as2[s]) + ad2n);
            e = val ? e : 0.f;
            den += e;
            if (act && val) {
                uint2 p = __ldg(&g24[s * 10 + gl]);
                float2 a = __half22float2(*(__half2*)&p.x);
                float2 b = __half22float2(*(__half2*)&p.y);
                acc.x += e * a.x; acc.y += e * a.y;
                acc.z += e * b.x; acc.w += e * b.y;
            }
        }
    }
    const float rinv = 1.f / (den + EPSV);

    float4 v = make_float4(-1e30f, -1e30f, -1e30f, -1e30f);
    if (act) {
        v = ((const float4*)b2)[gl];
        v.x += acc.x * rinv; v.y += acc.y * rinv;
        v.z += acc.z * rinv; v.w += acc.w * rinv;
    }
    float mx = act ? fmaxf(fmaxf(v.x, v.y), fmaxf(v.z, v.w)) : -1e30f;
    #pragma unroll
    for (int o = 1; o < 16; o <<= 1) {
        int srcl = gbase + ((gl + o) % 10);
        mx = fmaxf(mx, __shfl_sync(FULL, mx, srcl));
    }
    float sm = 0.f;
    if (act) sm = __expf(v.x - mx) + __expf(v.y - mx) + __expf(v.z - mx) + __expf(v.w - mx);
    float tot = sm;
    #pragma unroll
    for (int i = 1; i < 10; i++) {
        int srcl = gbase + ((gl + i) % 10);
        tot += __shfl_sync(FULL, sm, srcl);
    }
    float lse = mx + logf(tot);
    if (act)
        ((float4*)out)[n * 10 + gl] =
            make_float4(v.x - lse, v.y - lse, v.z - lse, v.w - lse);
}

// ---------------- launch ----------------
extern "C" void kernel_launch(void* const* d_in, const int* in_sizes, int n_in,
                              void* d_out, int out_size)
{
    const float* x      = (const float*)d_in[0];
    const int*   eidx   = (const int*)d_in[1];
    const float* W1     = (const float*)d_in[2];
    const float* a_src1 = (const float*)d_in[3];
    const float* a_dst1 = (const float*)d_in[4];
    const float* b1     = (const float*)d_in[5];
    const float* W2     = (const float*)d_in[6];
    const float* a_src2 = (const float*)d_in[7];
    const float* a_dst2 = (const float*)d_in[8];
    const float* b2     = (const float*)d_in[9];
    const int* src = eidx;
    const int* dst = eidx + EE;
    float* out = (float*)d_out;

    // Side stream + events for fork/join overlap of the CSR build with gemm1.
    static cudaStream_t sB = nullptr;
    static cudaEvent_t evFork = nullptr, evJoin = nullptr;
    if (sB == nullptr) {
        cudaStreamCreateWithFlags(&sB, cudaStreamNonBlocking);
        cudaEventCreateWithFlags(&evFork, cudaEventDisableTiming);
        cudaEventCreateWithFlags(&evJoin, cudaEventDisableTiming);
    }

    const int G1_SMEM = 2 * 128 * G1ROW * 2;   // 69632 B
    (void)cudaFuncSetAttribute(gemm1_kernel,
                               cudaFuncAttributeMaxDynamicSharedMemorySize, G1_SMEM);

    // fork: sort chain on sB runs concurrently with gemm1 on the main stream.
    cudaEventRecord(evFork, 0);
    cudaStreamWaitEvent(sB, evFork, 0);

    hist_kernel<<<(EE / 4 + 255) / 256, 256, 0, sB>>>(dst);                // 1
    scan1_kernel<<<98, 1024, 0, sB>>>();                                   // 2
    scanB_kernel<<<98, 1024, 0, sB>>>();                                   // 3
    gemm1_kernel<<<(NN + 127) / 128, 256, G1_SMEM>>>(x, W1, a_src1, a_dst1); // 4 (ncu)
    scatter_kernel<<<(EE / 4 + 255) / 256, 256, 0, sB>>>(src, dst);        // 5

    // join: agg1 needs both gemm1 outputs and the CSR
    cudaEventRecord(evJoin, sB);
    cudaStreamWaitEvent(0, evJoin, 0);

    agg1_kernel<<<NN / 8, 256>>>(b1);                                      // 6
    gemm2_kernel<<<(NN + 255) / 256, 256>>>(W2, a_src2, a_dst2);           // 7
    agg2_kernel<<<(NN / 3 + 8) / 8 + 1, 256>>>(b2, out);                   // 8
}